// round 2
// baseline (speedup 1.0000x reference)
#include <cuda_runtime.h>

#define NN 100000
#define DD 64
#define HH 256
#define EE 1000000

// ---------------- scratch (device globals; no allocs allowed) ----------------
__device__ __align__(256) float g_geo[NN * DD];     // geo segment sums
__device__ __align__(256) float g_trans[NN * DD];   // trans weighted sums
__device__ __align__(256) float g_cnt[NN];          // geo in-degree
__device__ __align__(16)  float g_w[2];             // semantic logits (sum over nodes)

// ---------------- zero scratch ----------------
__global__ void zero_kernel() {
    int idx = blockIdx.x * blockDim.x + threadIdx.x;  // 0 .. 1,599,999
    float4 z = make_float4(0.f, 0.f, 0.f, 0.f);
    if (idx < NN * DD / 4) {
        ((float4*)g_geo)[idx] = z;
        ((float4*)g_trans)[idx] = z;
    }
    if (idx < NN / 4) ((float4*)g_cnt)[idx] = z;
    if (idx == 0) { g_w[0] = 0.f; g_w[1] = 0.f; }
}

// ---------------- vectorized float atomic add (sm_90+) ----------------
__device__ __forceinline__ void red_add_v4(float* p, float4 v) {
    asm volatile("red.global.add.v4.f32 [%0], {%1, %2, %3, %4};"
                 :: "l"(p), "f"(v.x), "f"(v.y), "f"(v.z), "f"(v.w)
                 : "memory");
}

// ---------------- geo: copy_u + (sum, count) ----------------
// 16 threads per edge, each handles one float4 chunk of the 64-wide row.
__global__ void geo_scatter(const float* __restrict__ feat,
                            const int* __restrict__ src,
                            const int* __restrict__ dst) {
    int idx = blockIdx.x * blockDim.x + threadIdx.x;   // EE*16 = 16M threads
    int e = idx >> 4;
    int c = idx & 15;
    if (e >= EE) return;
    int s = __ldg(&src[e]);
    int d = __ldg(&dst[e]);
    float4 v = *(const float4*)(feat + s * DD + c * 4);
    red_add_v4(g_geo + d * DD + c * 4, v);
    if (c == 0) atomicAdd(&g_cnt[d], 1.0f);
}

// ---------------- trans: u_mul_e + sum ----------------
__global__ void trans_scatter(const float* __restrict__ feat,
                              const int* __restrict__ src,
                              const int* __restrict__ dst,
                              const float* __restrict__ w) {
    int idx = blockIdx.x * blockDim.x + threadIdx.x;
    int e = idx >> 4;
    int c = idx & 15;
    if (e >= EE) return;
    int s = __ldg(&src[e]);
    int d = __ldg(&dst[e]);
    float ww = __ldg(&w[e]);
    float4 v = *(const float4*)(feat + s * DD + c * 4);
    v.x *= ww; v.y *= ww; v.z *= ww; v.w *= ww;
    red_add_v4(g_trans + d * DD + c * 4, v);
}

// ---------------- fast, accurate-enough tanh ----------------
__device__ __forceinline__ float fast_tanh(float x) {
    x = fminf(fmaxf(x, -15.f), 15.f);
    float e = __expf(2.f * x);
    return __fdividef(e - 1.f, e + 1.f);   // rel err ~2^-21, fine vs 1e-3 budget
}

// ---------------- MLP + semantic-logit reduction ----------------
// Block: 256 threads, 32 nodes -> 64 A-rows (rows 0..31 = geo, 32..63 = trans).
// GEMM: A[64x64] @ W1[64x256], 4x16 microtile/thread, K=64 fully resident.
// Epilogue: tanh(+b1), dot W2, reduce per relation, atomic into g_w.
#define MLP_SMEM_FLOATS (64 * 68 + 64 * 256 + 256)
extern __shared__ float smem[];
__global__ void mlp_kernel(const float* __restrict__ W1,
                           const float* __restrict__ b1,
                           const float* __restrict__ W2) {
    float* sAT  = smem;                 // [64][68] A transposed, padded
    float* sB   = smem + 64 * 68;       // [64][256] = W1
    float* sRed = sB + 64 * 256;        // [256]
    int tid  = threadIdx.x;
    int base = blockIdx.x * 32;

    // Load A (z) transposed: r = row (node,k), d = feature
    for (int i = tid; i < 64 * 64; i += 256) {
        int r = i >> 6, d = i & 63;
        int node = base + (r & 31);
        float v;
        if (r < 32) {
            float c = g_cnt[node];
            v = (c > 0.f) ? g_geo[node * 64 + d] / c : 0.f;
        } else {
            v = g_trans[node * 64 + d];
        }
        sAT[d * 68 + r] = v;
    }
    // Load W1
    for (int i = tid; i < 64 * 256; i += 256) sB[i] = W1[i];
    __syncthreads();

    int tx = tid & 15;        // col group: cols tx*16 .. +15
    int ty = tid >> 4;        // row group: rows ty*4 .. +3

    float acc[4][16];
    #pragma unroll
    for (int i = 0; i < 4; i++)
        #pragma unroll
        for (int j = 0; j < 16; j++) acc[i][j] = 0.f;

    #pragma unroll 4
    for (int d = 0; d < 64; d++) {
        float4 a4 = *(float4*)&sAT[d * 68 + ty * 4];
        float a[4] = {a4.x, a4.y, a4.z, a4.w};
        const float4* bp = (const float4*)&sB[d * 256 + tx * 16];
        float4 b0 = bp[0], b1v = bp[1], b2 = bp[2], b3 = bp[3];
        float b[16] = {b0.x, b0.y, b0.z, b0.w, b1v.x, b1v.y, b1v.z, b1v.w,
                       b2.x, b2.y, b2.z, b2.w, b3.x, b3.y, b3.z, b3.w};
        #pragma unroll
        for (int i = 0; i < 4; i++)
            #pragma unroll
            for (int j = 0; j < 16; j++)
                acc[i][j] += a[i] * b[j];
    }

    // Epilogue: h = tanh(acc + b1), partial = sum h * W2
    float b1r[16], w2r[16];
    #pragma unroll
    for (int j = 0; j < 16; j++) {
        b1r[j] = __ldg(&b1[tx * 16 + j]);
        w2r[j] = __ldg(&W2[tx * 16 + j]);
    }
    float partial = 0.f;
    #pragma unroll
    for (int i = 0; i < 4; i++)
        #pragma unroll
        for (int j = 0; j < 16; j++)
            partial += fast_tanh(acc[i][j] + b1r[j]) * w2r[j];

    sRed[tid] = partial;
    __syncthreads();
    // rows ty<8 (tid<128) are geo(k=0); tid>=128 trans(k=1)
    for (int s = 64; s > 0; s >>= 1) {
        if ((tid & 127) < s) sRed[tid] += sRed[tid + s];
        __syncthreads();
    }
    if (tid == 0)   atomicAdd(&g_w[0], sRed[0]);
    if (tid == 128) atomicAdd(&g_w[1], sRed[128]);
}

// ---------------- final blend: out = beta0*geo + beta1*trans ----------------
__global__ void out_kernel(float* __restrict__ out) {
    int idx = blockIdx.x * blockDim.x + threadIdx.x;   // NN*16
    if (idx >= NN * 16) return;
    int n = idx >> 4;
    float w0 = g_w[0] * (1.0f / NN);
    float w1 = g_w[1] * (1.0f / NN);
    float beta0 = 1.f / (1.f + expf(w1 - w0));   // softmax over 2 logits
    float beta1 = 1.f - beta0;
    float c = g_cnt[n];
    float inv = (c > 0.f) ? 1.f / c : 0.f;
    float4 g = ((const float4*)g_geo)[idx];
    float4 t = ((const float4*)g_trans)[idx];
    float4 o;
    o.x = beta0 * (g.x * inv) + beta1 * t.x;
    o.y = beta0 * (g.y * inv) + beta1 * t.y;
    o.z = beta0 * (g.z * inv) + beta1 * t.z;
    o.w = beta0 * (g.w * inv) + beta1 * t.w;
    ((float4*)out)[idx] = o;
}

// ---------------- launch ----------------
extern "C" void kernel_launch(void* const* d_in, const int* in_sizes, int n_in,
                              void* d_out, int out_size) {
    const float* feat = (const float*)d_in[0];
    const int*   gsrc = (const int*)d_in[1];
    const int*   gdst = (const int*)d_in[2];
    const int*   tsrc = (const int*)d_in[3];
    const int*   tdst = (const int*)d_in[4];
    const float* tw   = (const float*)d_in[5];
    const float* W1   = (const float*)d_in[6];
    const float* b1   = (const float*)d_in[7];
    const float* W2   = (const float*)d_in[8];
    float* out = (float*)d_out;

    zero_kernel<<<6250, 256>>>();
    geo_scatter<<<(EE * 16) / 256, 256>>>(feat, gsrc, gdst);
    trans_scatter<<<(EE * 16) / 256, 256>>>(feat, tsrc, tdst, tw);

    int smem_bytes = MLP_SMEM_FLOATS * sizeof(float);   // ~84 KB
    cudaFuncSetAttribute(mlp_kernel, cudaFuncAttributeMaxDynamicSharedMemorySize, smem_bytes);
    mlp_kernel<<<NN / 32, 256, smem_bytes>>>(W1, b1, W2);

    out_kernel<<<(NN * 16) / 256, 256>>>(out);
}

// round 3
// speedup vs baseline: 1.6801x; 1.6801x over previous
#include <cuda_runtime.h>

#define NN 100000
#define DD 64
#define HH 256
#define EE 1000000

// ---------------- scratch (device globals; no allocs allowed) ----------------
__device__ __align__(256) float g_geo[NN * DD];     // geo segment sums
__device__ __align__(256) float g_trans[NN * DD];   // trans weighted sums
__device__ __align__(256) float g_cnt[NN];          // geo in-degree
__device__ __align__(16)  float g_w[2];             // semantic logits (sum over nodes)

// ---------------- zero scratch ----------------
__global__ void zero_kernel() {
    int idx = blockIdx.x * blockDim.x + threadIdx.x;
    float4 z = make_float4(0.f, 0.f, 0.f, 0.f);
    if (idx < NN * DD / 4) {
        ((float4*)g_geo)[idx] = z;
        ((float4*)g_trans)[idx] = z;
    }
    if (idx < NN / 4) ((float4*)g_cnt)[idx] = z;
    if (idx == 0) { g_w[0] = 0.f; g_w[1] = 0.f; }
}

// ---------------- vectorized float atomic add (sm_90+) ----------------
__device__ __forceinline__ void red_add_v4(float* p, float4 v) {
    asm volatile("red.global.add.v4.f32 [%0], {%1, %2, %3, %4};"
                 :: "l"(p), "f"(v.x), "f"(v.y), "f"(v.z), "f"(v.w)
                 : "memory");
}

// ---------------- geo: copy_u + (sum, count) ----------------
__global__ void geo_scatter(const float* __restrict__ feat,
                            const int* __restrict__ src,
                            const int* __restrict__ dst) {
    int idx = blockIdx.x * blockDim.x + threadIdx.x;   // EE*16
    int e = idx >> 4;
    int c = idx & 15;
    if (e >= EE) return;
    int s = __ldg(&src[e]);
    int d = __ldg(&dst[e]);
    float4 v = *(const float4*)(feat + s * DD + c * 4);
    red_add_v4(g_geo + d * DD + c * 4, v);
    if (c == 0) atomicAdd(&g_cnt[d], 1.0f);
}

// ---------------- trans: u_mul_e + sum ----------------
__global__ void trans_scatter(const float* __restrict__ feat,
                              const int* __restrict__ src,
                              const int* __restrict__ dst,
                              const float* __restrict__ w) {
    int idx = blockIdx.x * blockDim.x + threadIdx.x;
    int e = idx >> 4;
    int c = idx & 15;
    if (e >= EE) return;
    int s = __ldg(&src[e]);
    int d = __ldg(&dst[e]);
    float ww = __ldg(&w[e]);
    float4 v = *(const float4*)(feat + s * DD + c * 4);
    v.x *= ww; v.y *= ww; v.z *= ww; v.w *= ww;
    red_add_v4(g_trans + d * DD + c * 4, v);
}

// ---------------- fast, accurate-enough tanh ----------------
__device__ __forceinline__ float fast_tanh(float x) {
    x = fminf(fmaxf(x, -15.f), 15.f);
    float e = __expf(2.f * x);
    return __fdividef(e - 1.f, e + 1.f);
}

// ---------------- MLP + semantic-logit reduction ----------------
// Block: 256 threads, 32 nodes -> 64 A-rows (rows 0..31 = geo, 32..63 = trans).
// GEMM: A[64x64] @ W1[64x256]. Thread (tx,ty) computes rows ty*4..+3 and
// columns {j*64 + tx*4 + q : j=0..3, q=0..3}. The strided-quad column map
// makes every B LDS.128 phase conflict-free: bank = (tx*4)%32 spans 0..28.
#define MLP_SMEM_FLOATS (64 * 68 + 64 * 256 + 256)
extern __shared__ float smem[];
__global__ void __launch_bounds__(256, 2)
mlp_kernel(const float* __restrict__ W1,
           const float* __restrict__ b1,
           const float* __restrict__ W2) {
    float* sAT  = smem;                 // [64][68] A transposed, padded
    float* sB   = smem + 64 * 68;       // [64][256] = W1
    float* sRed = sB + 64 * 256;        // [256]
    int tid  = threadIdx.x;
    int base = blockIdx.x * 32;

    // Load A (z) transposed: r = row (node,k), d = feature
    for (int i = tid; i < 64 * 64; i += 256) {
        int r = i >> 6, d = i & 63;
        int node = base + (r & 31);
        float v;
        if (r < 32) {
            float c = g_cnt[node];
            v = (c > 0.f) ? g_geo[node * 64 + d] / c : 0.f;
        } else {
            v = g_trans[node * 64 + d];
        }
        sAT[d * 68 + r] = v;
    }
    // Load W1
    for (int i = tid; i < 64 * 256; i += 256) sB[i] = W1[i];
    __syncthreads();

    int tx = tid & 15;        // column quad selector
    int ty = tid >> 4;        // row group: rows ty*4 .. +3

    float acc[4][16];         // acc[i][j*4+q] -> row ty*4+i, col j*64+tx*4+q
    #pragma unroll
    for (int i = 0; i < 4; i++)
        #pragma unroll
        for (int j = 0; j < 16; j++) acc[i][j] = 0.f;

    #pragma unroll 4
    for (int d = 0; d < 64; d++) {
        float4 a4 = *(float4*)&sAT[d * 68 + ty * 4];
        float a[4] = {a4.x, a4.y, a4.z, a4.w};
        float b[16];
        #pragma unroll
        for (int j = 0; j < 4; j++) {
            float4 b4 = *(const float4*)&sB[d * 256 + j * 64 + tx * 4];
            b[j * 4 + 0] = b4.x; b[j * 4 + 1] = b4.y;
            b[j * 4 + 2] = b4.z; b[j * 4 + 3] = b4.w;
        }
        #pragma unroll
        for (int i = 0; i < 4; i++)
            #pragma unroll
            for (int j = 0; j < 16; j++)
                acc[i][j] += a[i] * b[j];
    }

    // Epilogue: h = tanh(acc + b1), partial = sum h * W2 (same strided cols)
    float b1r[16], w2r[16];
    #pragma unroll
    for (int j = 0; j < 4; j++) {
        float4 bb = *(const float4*)&b1[j * 64 + tx * 4];
        float4 ww = *(const float4*)&W2[j * 64 + tx * 4];
        b1r[j * 4 + 0] = bb.x; b1r[j * 4 + 1] = bb.y;
        b1r[j * 4 + 2] = bb.z; b1r[j * 4 + 3] = bb.w;
        w2r[j * 4 + 0] = ww.x; w2r[j * 4 + 1] = ww.y;
        w2r[j * 4 + 2] = ww.z; w2r[j * 4 + 3] = ww.w;
    }
    float partial = 0.f;
    #pragma unroll
    for (int i = 0; i < 4; i++)
        #pragma unroll
        for (int j = 0; j < 16; j++)
            partial += fast_tanh(acc[i][j] + b1r[j]) * w2r[j];

    sRed[tid] = partial;
    __syncthreads();
    // tid<128 are rows 0..31 (geo, k=0); tid>=128 rows 32..63 (trans, k=1)
    for (int s = 64; s > 0; s >>= 1) {
        if ((tid & 127) < s) sRed[tid] += sRed[tid + s];
        __syncthreads();
    }
    if (tid == 0)   atomicAdd(&g_w[0], sRed[0]);
    if (tid == 128) atomicAdd(&g_w[1], sRed[128]);
}

// ---------------- final blend: out = beta0*geo/cnt + beta1*trans ----------------
__global__ void out_kernel(float* __restrict__ out) {
    int idx = blockIdx.x * blockDim.x + threadIdx.x;   // NN*16
    if (idx >= NN * 16) return;
    int n = idx >> 4;
    float w0 = g_w[0] * (1.0f / NN);
    float w1 = g_w[1] * (1.0f / NN);
    float beta0 = 1.f / (1.f + expf(w1 - w0));
    float beta1 = 1.f - beta0;
    float c = g_cnt[n];
    float inv = (c > 0.f) ? 1.f / c : 0.f;
    float4 g = ((const float4*)g_geo)[idx];
    float4 t = ((const float4*)g_trans)[idx];
    float4 o;
    o.x = beta0 * (g.x * inv) + beta1 * t.x;
    o.y = beta0 * (g.y * inv) + beta1 * t.y;
    o.z = beta0 * (g.z * inv) + beta1 * t.z;
    o.w = beta0 * (g.w * inv) + beta1 * t.w;
    ((float4*)out)[idx] = o;
}

// ---------------- launch ----------------
extern "C" void kernel_launch(void* const* d_in, const int* in_sizes, int n_in,
                              void* d_out, int out_size) {
    const float* feat = (const float*)d_in[0];
    const int*   gsrc = (const int*)d_in[1];
    const int*   gdst = (const int*)d_in[2];
    const int*   tsrc = (const int*)d_in[3];
    const int*   tdst = (const int*)d_in[4];
    const float* tw   = (const float*)d_in[5];
    const float* W1   = (const float*)d_in[6];
    const float* b1   = (const float*)d_in[7];
    const float* W2   = (const float*)d_in[8];
    float* out = (float*)d_out;

    zero_kernel<<<6250, 256>>>();
    geo_scatter<<<(EE * 16) / 256, 256>>>(feat, gsrc, gdst);
    trans_scatter<<<(EE * 16) / 256, 256>>>(feat, tsrc, tdst, tw);

    int smem_bytes = MLP_SMEM_FLOATS * sizeof(float);   // ~84 KB
    cudaFuncSetAttribute(mlp_kernel, cudaFuncAttributeMaxDynamicSharedMemorySize, smem_bytes);
    mlp_kernel<<<NN / 32, 256, smem_bytes>>>(W1, b1, W2);

    out_kernel<<<(NN * 16) / 256, 256>>>(out);
}

// round 7
// speedup vs baseline: 3.2243x; 1.9192x over previous
#include <cuda_runtime.h>
#include <cuda_bf16.h>
#include <cstdint>

#define NN 100000
#define DD 64
#define HH 256
#define EE 1000000

#define ROWS_TOTAL 200000            // geo rows [0,NN) + trans rows [NN,2NN)
#define TILE_M 128
#define NTILES 1563                  // ceil(200000/128)
#define ROWS_PAD (NTILES * TILE_M)

// ---------------- scratch (device globals; no allocs) ----------------
__device__ __align__(256) float g_geo[NN * DD];
__device__ __align__(256) float g_trans[NN * DD];
__device__ __align__(256) float g_cnt[NN];
__device__ __align__(16)  float g_w[2];
__device__ __align__(256) __nv_bfloat16 g_w1hi[HH * DD];   // W1^T hi: [n][k]
__device__ __align__(256) __nv_bfloat16 g_w1lo[HH * DD];   // W1^T lo

#define SWZ128(o) ((o) ^ (((o) >> 3) & 0x70))

__device__ __forceinline__ uint32_t smem_u32(const void* p) {
    uint32_t a;
    asm("{ .reg .u64 t; cvta.to.shared.u64 t, %1; cvt.u32.u64 %0, t; }" : "=r"(a) : "l"(p));
    return a;
}

// ---------------- zero scratch ----------------
__global__ void zero_kernel() {
    int idx = blockIdx.x * blockDim.x + threadIdx.x;
    float4 z = make_float4(0.f, 0.f, 0.f, 0.f);
    if (idx < NN * DD / 4) {
        ((float4*)g_geo)[idx] = z;
        ((float4*)g_trans)[idx] = z;
    }
    if (idx < NN / 4) ((float4*)g_cnt)[idx] = z;
    if (idx == 0) { g_w[0] = 0.f; g_w[1] = 0.f; }
}

// ---------------- vectorized float atomic add ----------------
__device__ __forceinline__ void red_add_v4(float* p, float4 v) {
    asm volatile("red.global.add.v4.f32 [%0], {%1, %2, %3, %4};"
                 :: "l"(p), "f"(v.x), "f"(v.y), "f"(v.z), "f"(v.w) : "memory");
}

// ---------------- merged scatter: geo then trans ----------------
__global__ void scatter_kernel(const float* __restrict__ feat,
                               const int* __restrict__ gsrc,
                               const int* __restrict__ gdst,
                               const int* __restrict__ tsrc,
                               const int* __restrict__ tdst,
                               const float* __restrict__ tw) {
    int idx = blockIdx.x * blockDim.x + threadIdx.x;   // 2*EE*16
    int half = (idx >= EE * 16);
    int i = half ? idx - EE * 16 : idx;
    int e = i >> 4, c = i & 15;
    if (e >= EE) return;
    if (!half) {
        int s = __ldg(&gsrc[e]);
        int d = __ldg(&gdst[e]);
        float4 v = *(const float4*)(feat + s * DD + c * 4);
        red_add_v4(g_geo + d * DD + c * 4, v);
        if (c == 0) atomicAdd(&g_cnt[d], 1.0f);
    } else {
        int s = __ldg(&tsrc[e]);
        int d = __ldg(&tdst[e]);
        float ww = __ldg(&tw[e]);
        float4 v = *(const float4*)(feat + s * DD + c * 4);
        v.x *= ww; v.y *= ww; v.z *= ww; v.w *= ww;
        red_add_v4(g_trans + d * DD + c * 4, v);
    }
}

// ---------------- prep: W1^T -> bf16 hi/lo ----------------
__global__ void prep_w1(const float* __restrict__ W1) {
    int idx = blockIdx.x * blockDim.x + threadIdx.x;  // HH*DD
    if (idx >= HH * DD) return;
    int n = idx >> 6, k = idx & 63;
    float v = __ldg(&W1[k * HH + n]);
    __nv_bfloat16 hi = __float2bfloat16_rn(v);
    g_w1hi[idx] = hi;
    g_w1lo[idx] = __float2bfloat16_rn(v - __bfloat162float(hi));
}

// ---------------- helpers ----------------
__device__ __forceinline__ uint32_t pack_bf2(float lo, float hi) {
    float2 f = make_float2(lo, hi);
    __nv_bfloat162 h = __float22bfloat162_rn(f);   // .x = low half
    return *(uint32_t*)&h;
}
__device__ __forceinline__ void mma_bf16(float& c0, float& c1, float& c2, float& c3,
                                         uint32_t a0, uint32_t a1, uint32_t a2, uint32_t a3,
                                         uint32_t b0, uint32_t b1) {
    asm volatile(
        "mma.sync.aligned.m16n8k16.row.col.f32.bf16.bf16.f32 "
        "{%0,%1,%2,%3}, {%4,%5,%6,%7}, {%8,%9}, {%0,%1,%2,%3};"
        : "+f"(c0), "+f"(c1), "+f"(c2), "+f"(c3)
        : "r"(a0), "r"(a1), "r"(a2), "r"(a3), "r"(b0), "r"(b1));
}
__device__ __forceinline__ void ldsm_x4(uint32_t& r0, uint32_t& r1, uint32_t& r2, uint32_t& r3,
                                        uint32_t addr) {
    asm volatile("ldmatrix.sync.aligned.m8n8.x4.shared.b16 {%0,%1,%2,%3}, [%4];"
                 : "=r"(r0), "=r"(r1), "=r"(r2), "=r"(r3) : "r"(addr));
}
__device__ __forceinline__ float tanh_fast(float x) {
    float h;
    asm("tanh.approx.f32 %0, %1;" : "=f"(h) : "f"(x));
    return h;
}

// ---------------- MLP: HMMA bf16 split GEMM + tanh + W2 dot ----------------
// Grid: NTILES blocks x 128 threads (4 warps). Warp w owns rows base..base+31.
// D = Ahi*Bhi + Ahi*Blo (A-rounding error cancels in the mean over rows).
#define SB_HI 0
#define SB_LO 32768
#define MLP_SMEM 65536

extern __shared__ char msmem[];
__global__ void __launch_bounds__(128)
mlp_kernel(const float* __restrict__ b1, const float* __restrict__ W2) {
    uint32_t sbase = smem_u32(msmem);
    int tid = threadIdx.x;
    int wid = tid >> 5, lid = tid & 31;
    int q = lid & 3;

    // Stage W1^T hi/lo into SW128-swizzled smem: [256 rows][128B]
    {
        const uint4* shi = (const uint4*)g_w1hi;
        const uint4* slo = (const uint4*)g_w1lo;
        #pragma unroll
        for (int i = 0; i < 16; i++) {
            int idx = i * 128 + tid;            // 2048 uint4
            int o = idx * 16;
            int sw = SWZ128(o);
            *(uint4*)(msmem + SB_HI + sw) = shi[idx];
            *(uint4*)(msmem + SB_LO + sw) = slo[idx];
        }
    }
    __syncthreads();

    int base = blockIdx.x * TILE_M + wid * 32;

    // ---- Build A fragments (bf16 hi) directly from fp32 z with inline cvt ----
    uint32_t A[2][4][4];
    #pragma unroll
    for (int t = 0; t < 2; t++) {
        int ra = base + t * 16 + (lid >> 2);
        int rb = ra + 8;
        const float *pa, *pb;
        float sa, sb;
        {
            int r = ra;
            if (r < NN) { float c = __ldg(&g_cnt[r]); sa = (c > 0.f) ? 1.f / c : 0.f; pa = g_geo + r * DD; }
            else { int rr = r - NN; if (rr >= NN) { rr = 0; sa = 0.f; } else sa = 1.f; pa = g_trans + rr * DD; }
        }
        {
            int r = rb;
            if (r < NN) { float c = __ldg(&g_cnt[r]); sb = (c > 0.f) ? 1.f / c : 0.f; pb = g_geo + r * DD; }
            else { int rr = r - NN; if (rr >= NN) { rr = 0; sb = 0.f; } else sb = 1.f; pb = g_trans + rr * DD; }
        }
        #pragma unroll
        for (int kc = 0; kc < 4; kc++) {
            int k0 = kc * 16 + q * 2;
            float2 v0 = __ldg((const float2*)(pa + k0));
            float2 v1 = __ldg((const float2*)(pb + k0));
            float2 v2 = __ldg((const float2*)(pa + k0 + 8));
            float2 v3 = __ldg((const float2*)(pb + k0 + 8));
            A[t][kc][0] = pack_bf2(v0.x * sa, v0.y * sa);
            A[t][kc][1] = pack_bf2(v1.x * sb, v1.y * sb);
            A[t][kc][2] = pack_bf2(v2.x * sa, v2.y * sa);
            A[t][kc][3] = pack_bf2(v3.x * sb, v3.y * sb);
        }
    }

    // ldmatrix per-lane address offsets (two kc-pairs per matrix)
    int rl = lid & 7;
    int quad = lid >> 3;
    int off0 = rl * 128 + (((quad)     ^ rl) << 4);   // kc 0,1
    int off1 = rl * 128 + (((quad + 4) ^ rl) << 4);   // kc 2,3

    float p00 = 0.f, p01 = 0.f, p10 = 0.f, p11 = 0.f;  // row partials

    #pragma unroll 4
    for (int nc = 0; nc < 32; nc++) {
        uint32_t nb = nc * 1024;
        uint32_t bh[4][2], bl[4][2];
        ldsm_x4(bh[0][0], bh[0][1], bh[1][0], bh[1][1], sbase + SB_HI + nb + off0);
        ldsm_x4(bh[2][0], bh[2][1], bh[3][0], bh[3][1], sbase + SB_HI + nb + off1);
        ldsm_x4(bl[0][0], bl[0][1], bl[1][0], bl[1][1], sbase + SB_LO + nb + off0);
        ldsm_x4(bl[2][0], bl[2][1], bl[3][0], bl[3][1], sbase + SB_LO + nb + off1);

        int col0 = nc * 8 + q * 2;
        float2 b1v = __ldg((const float2*)(b1 + col0));
        float2 w2v = __ldg((const float2*)(W2 + col0));

        #pragma unroll
        for (int t = 0; t < 2; t++) {
            float c0 = 0.f, c1 = 0.f, c2 = 0.f, c3 = 0.f;
            #pragma unroll
            for (int kc = 0; kc < 4; kc++) {
                mma_bf16(c0, c1, c2, c3,
                         A[t][kc][0], A[t][kc][1], A[t][kc][2], A[t][kc][3],
                         bh[kc][0], bh[kc][1]);
                mma_bf16(c0, c1, c2, c3,
                         A[t][kc][0], A[t][kc][1], A[t][kc][2], A[t][kc][3],
                         bl[kc][0], bl[kc][1]);
            }
            float u = tanh_fast(c0 + b1v.x) * w2v.x + tanh_fast(c1 + b1v.y) * w2v.y;
            float v = tanh_fast(c2 + b1v.x) * w2v.x + tanh_fast(c3 + b1v.y) * w2v.y;
            if (t == 0) { p00 += u; p01 += v; } else { p10 += u; p11 += v; }
        }
    }

    // Mask padded rows, reduce, accumulate semantic logits
    int r00 = base + (lid >> 2);
    float s = 0.f;
    if (r00      < ROWS_TOTAL) s += p00;
    if (r00 + 8  < ROWS_TOTAL) s += p01;
    if (r00 + 16 < ROWS_TOTAL) s += p10;
    if (r00 + 24 < ROWS_TOTAL) s += p11;
    #pragma unroll
    for (int sh = 16; sh > 0; sh >>= 1) s += __shfl_xor_sync(0xFFFFFFFFu, s, sh);
    if (lid == 0) {
        int rel = (base < NN) ? 0 : 1;   // NN % 32 == 0 -> warp-uniform
        atomicAdd(&g_w[rel], s);
    }
}

// ---------------- final blend ----------------
__global__ void out_kernel(float* __restrict__ out) {
    int idx = blockIdx.x * blockDim.x + threadIdx.x;   // NN*16
    if (idx >= NN * 16) return;
    int n = idx >> 4;
    float w0 = g_w[0] * (1.0f / NN);
    float w1 = g_w[1] * (1.0f / NN);
    float beta0 = 1.f / (1.f + expf(w1 - w0));
    float beta1 = 1.f - beta0;
    float c = g_cnt[n];
    float inv = (c > 0.f) ? 1.f / c : 0.f;
    float4 g = ((const float4*)g_geo)[idx];
    float4 t = ((const float4*)g_trans)[idx];
    float4 o;
    o.x = beta0 * (g.x * inv) + beta1 * t.x;
    o.y = beta0 * (g.y * inv) + beta1 * t.y;
    o.z = beta0 * (g.z * inv) + beta1 * t.z;
    o.w = beta0 * (g.w * inv) + beta1 * t.w;
    ((float4*)out)[idx] = o;
}

// ---------------- launch ----------------
extern "C" void kernel_launch(void* const* d_in, const int* in_sizes, int n_in,
                              void* d_out, int out_size) {
    const float* feat = (const float*)d_in[0];
    const int*   gsrc = (const int*)d_in[1];
    const int*   gdst = (const int*)d_in[2];
    const int*   tsrc = (const int*)d_in[3];
    const int*   tdst = (const int*)d_in[4];
    const float* tw   = (const float*)d_in[5];
    const float* W1   = (const float*)d_in[6];
    const float* b1   = (const float*)d_in[7];
    const float* W2   = (const float*)d_in[8];
    float* out = (float*)d_out;

    zero_kernel<<<6250, 256>>>();
    prep_w1<<<64, 256>>>(W1);
    scatter_kernel<<<(2 * EE * 16) / 256, 256>>>(feat, gsrc, gdst, tsrc, tdst, tw);

    cudaFuncSetAttribute(mlp_kernel, cudaFuncAttributeMaxDynamicSharedMemorySize, MLP_SMEM);
    mlp_kernel<<<NTILES, 128, MLP_SMEM>>>(b1, W2);

    out_kernel<<<(NN * 16) / 256, 256>>>(out);
}

// round 8
// speedup vs baseline: 3.9709x; 1.2315x over previous
#include <cuda_runtime.h>
#include <cuda_bf16.h>
#include <cstdint>

#define NN 100000
#define DD 64
#define HH 256
#define EE 1000000

#define ROWS_TOTAL 200000            // geo rows [0,NN) + trans rows [NN,2NN)
#define TILE_M 128
#define NTILES 1563                  // ceil(200000/128)
#define ROWS_PAD (NTILES * TILE_M)   // 200064
#define NSEG (2 * NN)                // 200000 segments (geo + trans)
#define SCAN_CH 1024
#define NB_SCAN 196                  // ceil(NSEG / SCAN_CH)

// ---------------- scratch (device globals; no allocs) ----------------
__device__ __align__(256) float g_z[ROWS_PAD * DD];   // geo-mean rows then trans rows
__device__ __align__(256) int   g_deg[NSEG];
__device__ __align__(256) int   g_rowptr[NSEG + 1];
__device__ __align__(256) int   g_cursor[NSEG];
__device__ __align__(256) int   g_esrc[2 * EE];
__device__ __align__(256) float g_ew[2 * EE];         // weights (trans region only)
__device__ int g_bsum[NB_SCAN];
__device__ int g_bbase[NB_SCAN];
__device__ __align__(16)  float g_w[2];
__device__ __align__(256) __nv_bfloat16 g_w1hi[HH * DD];   // W1^T hi: [n][k]
__device__ __align__(256) __nv_bfloat16 g_w1lo[HH * DD];   // W1^T lo

#define SWZ128(o) ((o) ^ (((o) >> 3) & 0x70))

__device__ __forceinline__ uint32_t smem_u32(const void* p) {
    uint32_t a;
    asm("{ .reg .u64 t; cvta.to.shared.u64 t, %1; cvt.u32.u64 %0, t; }" : "=r"(a) : "l"(p));
    return a;
}

// ---------------- zero: deg, logits, z padding tail ----------------
__global__ void zero_kernel() {
    int idx = blockIdx.x * blockDim.x + threadIdx.x;   // 196*256 = 50176
    if (idx < NSEG / 4) ((int4*)g_deg)[idx] = make_int4(0, 0, 0, 0);
    if (idx < (ROWS_PAD - ROWS_TOTAL) * DD / 4)        // 1024 float4s
        ((float4*)g_z)[ROWS_TOTAL * DD / 4 + idx] = make_float4(0.f, 0.f, 0.f, 0.f);
    if (idx == 0) { g_w[0] = 0.f; g_w[1] = 0.f; }
}

// ---------------- histogram of dst degrees (both relations) ----------------
__global__ void hist_kernel(const int* __restrict__ gdst,
                            const int* __restrict__ tdst) {
    int i = blockIdx.x * blockDim.x + threadIdx.x;
    if (i >= 2 * EE) return;
    if (i < EE) atomicAdd(&g_deg[__ldg(&gdst[i])], 1);
    else        atomicAdd(&g_deg[NN + __ldg(&tdst[i - EE])], 1);
}

// ---------------- 3-phase exclusive scan over g_deg -> g_rowptr ----------------
__global__ void scan_a() {
    __shared__ int sd[256];
    int b = blockIdx.x, t = threadIdx.x;
    int base = b * SCAN_CH;
    int sum = 0;
    for (int i = t; i < SCAN_CH; i += 256) {
        int idx = base + i;
        if (idx < NSEG) sum += g_deg[idx];
    }
    sd[t] = sum; __syncthreads();
    for (int s = 128; s > 0; s >>= 1) {
        if (t < s) sd[t] += sd[t + s];
        __syncthreads();
    }
    if (t == 0) g_bsum[b] = sd[0];
}
__global__ void scan_b() {
    __shared__ int sb[256];
    int t = threadIdx.x;
    int v = (t < NB_SCAN) ? g_bsum[t] : 0;
    sb[t] = v; __syncthreads();
    for (int off = 1; off < 256; off <<= 1) {
        int x = (t >= off) ? sb[t - off] : 0;
        __syncthreads();
        sb[t] += x;
        __syncthreads();
    }
    if (t < NB_SCAN) g_bbase[t] = sb[t] - v;   // exclusive
}
__global__ void scan_c() {
    __shared__ int sb[256];
    int b = blockIdx.x, t = threadIdx.x;
    int base = b * SCAN_CH + t * 4;
    int vals[4];
    int tot = 0;
    #pragma unroll
    for (int i = 0; i < 4; i++) {
        int idx = base + i;
        vals[i] = (idx < NSEG) ? g_deg[idx] : 0;
        tot += vals[i];
    }
    sb[t] = tot; __syncthreads();
    for (int off = 1; off < 256; off <<= 1) {
        int x = (t >= off) ? sb[t - off] : 0;
        __syncthreads();
        sb[t] += x;
        __syncthreads();
    }
    int run = g_bbase[b] + sb[t] - tot;        // exclusive thread base
    #pragma unroll
    for (int i = 0; i < 4; i++) {
        int idx = base + i;
        if (idx < NSEG) { g_rowptr[idx] = run; g_cursor[idx] = run; }
        run += vals[i];
    }
    if (b == 0 && t == 0) g_rowptr[NSEG] = 2 * EE;
}

// ---------------- fill CSR edge arrays ----------------
__global__ void fill_kernel(const int* __restrict__ gsrc,
                            const int* __restrict__ gdst,
                            const int* __restrict__ tsrc,
                            const int* __restrict__ tdst,
                            const float* __restrict__ tw) {
    int i = blockIdx.x * blockDim.x + threadIdx.x;
    if (i >= 2 * EE) return;
    if (i < EE) {
        int d = __ldg(&gdst[i]);
        int pos = atomicAdd(&g_cursor[d], 1);
        g_esrc[pos] = __ldg(&gsrc[i]);
    } else {
        int j = i - EE;
        int d = NN + __ldg(&tdst[j]);
        int pos = atomicAdd(&g_cursor[d], 1);
        g_esrc[pos] = __ldg(&tsrc[j]);
        g_ew[pos] = __ldg(&tw[j]);
    }
}

// ---------------- gather-SpMM: one warp per segment, register accumulation ----
__global__ void __launch_bounds__(256)
gather_kernel(const float* __restrict__ feat) {
    int gw = (blockIdx.x * blockDim.x + threadIdx.x) >> 5;  // 0 .. NSEG-1
    int lane = threadIdx.x & 31;
    if (gw >= NSEG) return;
    int start = g_rowptr[gw];
    int end   = g_rowptr[gw + 1];
    const float2* f2 = (const float2*)feat;
    float ax = 0.f, ay = 0.f;

    if (gw < NN) {
        // geo: plain sum then mean
        for (int jb = start; jb < end; jb += 32) {
            int n32 = min(32, end - jb);
            int e = (lane < n32) ? __ldg(&g_esrc[jb + lane]) : 0;
            int t = 0;
            for (; t + 4 <= n32; t += 4) {
                int s0 = __shfl_sync(0xFFFFFFFFu, e, t);
                int s1 = __shfl_sync(0xFFFFFFFFu, e, t + 1);
                int s2 = __shfl_sync(0xFFFFFFFFu, e, t + 2);
                int s3 = __shfl_sync(0xFFFFFFFFu, e, t + 3);
                float2 v0 = __ldg(&f2[s0 * 32 + lane]);
                float2 v1 = __ldg(&f2[s1 * 32 + lane]);
                float2 v2 = __ldg(&f2[s2 * 32 + lane]);
                float2 v3 = __ldg(&f2[s3 * 32 + lane]);
                ax += v0.x + v1.x + v2.x + v3.x;
                ay += v0.y + v1.y + v2.y + v3.y;
            }
            for (; t < n32; t++) {
                int s = __shfl_sync(0xFFFFFFFFu, e, t);
                float2 v = __ldg(&f2[s * 32 + lane]);
                ax += v.x; ay += v.y;
            }
        }
        int deg = end - start;
        float inv = (deg > 0) ? 1.f / (float)deg : 0.f;
        ax *= inv; ay *= inv;
    } else {
        // trans: weighted sum
        for (int jb = start; jb < end; jb += 32) {
            int n32 = min(32, end - jb);
            bool ok = lane < n32;
            int e   = ok ? __ldg(&g_esrc[jb + lane]) : 0;
            float w = ok ? __ldg(&g_ew[jb + lane]) : 0.f;
            int t = 0;
            for (; t + 4 <= n32; t += 4) {
                int s0 = __shfl_sync(0xFFFFFFFFu, e, t);
                int s1 = __shfl_sync(0xFFFFFFFFu, e, t + 1);
                int s2 = __shfl_sync(0xFFFFFFFFu, e, t + 2);
                int s3 = __shfl_sync(0xFFFFFFFFu, e, t + 3);
                float w0 = __shfl_sync(0xFFFFFFFFu, w, t);
                float w1 = __shfl_sync(0xFFFFFFFFu, w, t + 1);
                float w2 = __shfl_sync(0xFFFFFFFFu, w, t + 2);
                float w3 = __shfl_sync(0xFFFFFFFFu, w, t + 3);
                float2 v0 = __ldg(&f2[s0 * 32 + lane]);
                float2 v1 = __ldg(&f2[s1 * 32 + lane]);
                float2 v2 = __ldg(&f2[s2 * 32 + lane]);
                float2 v3 = __ldg(&f2[s3 * 32 + lane]);
                ax += v0.x * w0 + v1.x * w1 + v2.x * w2 + v3.x * w3;
                ay += v0.y * w0 + v1.y * w1 + v2.y * w2 + v3.y * w3;
            }
            for (; t < n32; t++) {
                int s  = __shfl_sync(0xFFFFFFFFu, e, t);
                float ww = __shfl_sync(0xFFFFFFFFu, w, t);
                float2 v = __ldg(&f2[s * 32 + lane]);
                ax += v.x * ww; ay += v.y * ww;
            }
        }
    }
    float2 o; o.x = ax; o.y = ay;
    ((float2*)g_z)[gw * 32 + lane] = o;
}

// ---------------- prep: W1^T -> bf16 hi/lo ----------------
__global__ void prep_w1(const float* __restrict__ W1) {
    int idx = blockIdx.x * blockDim.x + threadIdx.x;
    if (idx >= HH * DD) return;
    int n = idx >> 6, k = idx & 63;
    float v = __ldg(&W1[k * HH + n]);
    __nv_bfloat16 hi = __float2bfloat16_rn(v);
    g_w1hi[idx] = hi;
    g_w1lo[idx] = __float2bfloat16_rn(v - __bfloat162float(hi));
}

// ---------------- MMA helpers ----------------
__device__ __forceinline__ uint32_t pack_bf2(float lo, float hi) {
    float2 f = make_float2(lo, hi);
    __nv_bfloat162 h = __float22bfloat162_rn(f);
    return *(uint32_t*)&h;
}
__device__ __forceinline__ void mma_bf16(float& c0, float& c1, float& c2, float& c3,
                                         uint32_t a0, uint32_t a1, uint32_t a2, uint32_t a3,
                                         uint32_t b0, uint32_t b1) {
    asm volatile(
        "mma.sync.aligned.m16n8k16.row.col.f32.bf16.bf16.f32 "
        "{%0,%1,%2,%3}, {%4,%5,%6,%7}, {%8,%9}, {%0,%1,%2,%3};"
        : "+f"(c0), "+f"(c1), "+f"(c2), "+f"(c3)
        : "r"(a0), "r"(a1), "r"(a2), "r"(a3), "r"(b0), "r"(b1));
}
__device__ __forceinline__ void ldsm_x4(uint32_t& r0, uint32_t& r1, uint32_t& r2, uint32_t& r3,
                                        uint32_t addr) {
    asm volatile("ldmatrix.sync.aligned.m8n8.x4.shared.b16 {%0,%1,%2,%3}, [%4];"
                 : "=r"(r0), "=r"(r1), "=r"(r2), "=r"(r3) : "r"(addr));
}
__device__ __forceinline__ float tanh_fast(float x) {
    float h;
    asm("tanh.approx.f32 %0, %1;" : "=f"(h) : "f"(x));
    return h;
}

// ---------------- MLP: persistent HMMA bf16 split GEMM + tanh + W2 dot -------
#define SB_HI 0
#define SB_LO 32768
#define MLP_SMEM 65536
#define MLP_GRID 444                 // 3 CTAs/SM x 148 SMs

extern __shared__ char msmem[];
__global__ void __launch_bounds__(128, 3)
mlp_kernel(const float* __restrict__ b1, const float* __restrict__ W2) {
    uint32_t sbase = smem_u32(msmem);
    int tid = threadIdx.x;
    int wid = tid >> 5, lid = tid & 31;
    int q = lid & 3;

    // Stage W1^T hi/lo into SW128-swizzled smem once per block
    {
        const uint4* shi = (const uint4*)g_w1hi;
        const uint4* slo = (const uint4*)g_w1lo;
        #pragma unroll
        for (int i = 0; i < 16; i++) {
            int idx = i * 128 + tid;
            int o = idx * 16;
            int sw = SWZ128(o);
            *(uint4*)(msmem + SB_HI + sw) = shi[idx];
            *(uint4*)(msmem + SB_LO + sw) = slo[idx];
        }
    }
    __syncthreads();

    int rl = lid & 7;
    int quad = lid >> 3;
    int off0 = rl * 128 + (((quad)     ^ rl) << 4);
    int off1 = rl * 128 + (((quad + 4) ^ rl) << 4);

    float sg = 0.f, st = 0.f;    // per-warp logit accumulators (geo / trans)

    for (int tile = blockIdx.x; tile < NTILES; tile += gridDim.x) {
        int base = tile * TILE_M + wid * 32;

        // A fragments (bf16 hi) from fp32 g_z
        uint32_t A[2][4][4];
        #pragma unroll
        for (int t = 0; t < 2; t++) {
            int ra = base + t * 16 + (lid >> 2);
            const float* pa = g_z + (size_t)ra * DD;
            const float* pb = pa + 8 * DD;
            #pragma unroll
            for (int kc = 0; kc < 4; kc++) {
                int k0 = kc * 16 + q * 2;
                float2 v0 = __ldg((const float2*)(pa + k0));
                float2 v1 = __ldg((const float2*)(pb + k0));
                float2 v2 = __ldg((const float2*)(pa + k0 + 8));
                float2 v3 = __ldg((const float2*)(pb + k0 + 8));
                A[t][kc][0] = pack_bf2(v0.x, v0.y);
                A[t][kc][1] = pack_bf2(v1.x, v1.y);
                A[t][kc][2] = pack_bf2(v2.x, v2.y);
                A[t][kc][3] = pack_bf2(v3.x, v3.y);
            }
        }

        float p00 = 0.f, p01 = 0.f, p10 = 0.f, p11 = 0.f;

        #pragma unroll 4
        for (int nc = 0; nc < 32; nc++) {
            uint32_t nb = nc * 1024;
            uint32_t bh[4][2], bl[4][2];
            ldsm_x4(bh[0][0], bh[0][1], bh[1][0], bh[1][1], sbase + SB_HI + nb + off0);
            ldsm_x4(bh[2][0], bh[2][1], bh[3][0], bh[3][1], sbase + SB_HI + nb + off1);
            ldsm_x4(bl[0][0], bl[0][1], bl[1][0], bl[1][1], sbase + SB_LO + nb + off0);
            ldsm_x4(bl[2][0], bl[2][1], bl[3][0], bl[3][1], sbase + SB_LO + nb + off1);

            int col0 = nc * 8 + q * 2;
            float2 b1v = __ldg((const float2*)(b1 + col0));
            float2 w2v = __ldg((const float2*)(W2 + col0));

            #pragma unroll
            for (int t = 0; t < 2; t++) {
                float c0 = 0.f, c1 = 0.f, c2 = 0.f, c3 = 0.f;
                #pragma unroll
                for (int kc = 0; kc < 4; kc++) {
                    mma_bf16(c0, c1, c2, c3,
                             A[t][kc][0], A[t][kc][1], A[t][kc][2], A[t][kc][3],
                             bh[kc][0], bh[kc][1]);
                    mma_bf16(c0, c1, c2, c3,
                             A[t][kc][0], A[t][kc][1], A[t][kc][2], A[t][kc][3],
                             bl[kc][0], bl[kc][1]);
                }
                float u = tanh_fast(c0 + b1v.x) * w2v.x + tanh_fast(c1 + b1v.y) * w2v.y;
                float v = tanh_fast(c2 + b1v.x) * w2v.x + tanh_fast(c3 + b1v.y) * w2v.y;
                if (t == 0) { p00 += u; p01 += v; } else { p10 += u; p11 += v; }
            }
        }

        // Mask padded rows, accumulate into per-relation accumulators
        int r00 = base + (lid >> 2);
        float s = 0.f;
        if (r00      < ROWS_TOTAL) s += p00;
        if (r00 + 8  < ROWS_TOTAL) s += p01;
        if (r00 + 16 < ROWS_TOTAL) s += p10;
        if (r00 + 24 < ROWS_TOTAL) s += p11;
        if (base < NN) sg += s; else st += s;   // NN % 32 == 0 -> warp-uniform
    }

    #pragma unroll
    for (int sh = 16; sh > 0; sh >>= 1) {
        sg += __shfl_xor_sync(0xFFFFFFFFu, sg, sh);
        st += __shfl_xor_sync(0xFFFFFFFFu, st, sh);
    }
    if (lid == 0) {
        atomicAdd(&g_w[0], sg);
        atomicAdd(&g_w[1], st);
    }
}

// ---------------- final blend ----------------
__global__ void out_kernel(float* __restrict__ out) {
    int idx = blockIdx.x * blockDim.x + threadIdx.x;   // NN*16
    if (idx >= NN * 16) return;
    float w0 = g_w[0] * (1.0f / NN);
    float w1 = g_w[1] * (1.0f / NN);
    float beta0 = 1.f / (1.f + expf(w1 - w0));
    float beta1 = 1.f - beta0;
    float4 a = ((const float4*)g_z)[idx];              // geo mean rows
    float4 b = ((const float4*)g_z)[NN * 16 + idx];    // trans rows
    float4 o;
    o.x = beta0 * a.x + beta1 * b.x;
    o.y = beta0 * a.y + beta1 * b.y;
    o.z = beta0 * a.z + beta1 * b.z;
    o.w = beta0 * a.w + beta1 * b.w;
    ((float4*)out)[idx] = o;
}

// ---------------- launch ----------------
extern "C" void kernel_launch(void* const* d_in, const int* in_sizes, int n_in,
                              void* d_out, int out_size) {
    const float* feat = (const float*)d_in[0];
    const int*   gsrc = (const int*)d_in[1];
    const int*   gdst = (const int*)d_in[2];
    const int*   tsrc = (const int*)d_in[3];
    const int*   tdst = (const int*)d_in[4];
    const float* tw   = (const float*)d_in[5];
    const float* W1   = (const float*)d_in[6];
    const float* b1   = (const float*)d_in[7];
    const float* W2   = (const float*)d_in[8];
    float* out = (float*)d_out;

    zero_kernel<<<196, 256>>>();
    prep_w1<<<64, 256>>>(W1);
    hist_kernel<<<(2 * EE + 255) / 256, 256>>>(gdst, tdst);
    scan_a<<<NB_SCAN, 256>>>();
    scan_b<<<1, 256>>>();
    scan_c<<<NB_SCAN, 256>>>();
    fill_kernel<<<(2 * EE + 255) / 256, 256>>>(gsrc, gdst, tsrc, tdst, tw);
    gather_kernel<<<(NSEG + 7) / 8, 256>>>(feat);

    cudaFuncSetAttribute(mlp_kernel, cudaFuncAttributeMaxDynamicSharedMemorySize, MLP_SMEM);
    mlp_kernel<<<MLP_GRID, 128, MLP_SMEM>>>(b1, W2);

    out_kernel<<<(NN * 16 + 255) / 256, 256>>>(out);
}